// round 1
// baseline (speedup 1.0000x reference)
#include <cuda_runtime.h>
#include <cstdint>

#define CI  256   // channels
#define II  16    // irrep dim
#define NK3 23
#define NK2 4
#define NT3 816   // C(18,3) sorted triples p<=q<=j
#define NT2 136   // sorted pairs p<=q
#define NCOEFF (NT3 + NT2 + II)   // 968
#define BMAX 4096

// ---------------- static device scratch (no allocation allowed) ----------------
__device__ float              g_P[NT3 * NK3];          // symmetrized U3 basis
__device__ unsigned long long g_coeff[CI * 1024];      // per-channel packed (v,v) coeffs
__device__ float              g_out1[BMAX * CI];       // (B, C) intermediate

// ---------------- f32x2 packed-math helpers (sm_103a FFMA2 path) ----------------
__device__ __forceinline__ unsigned long long pk2(float lo, float hi) {
    unsigned long long r;
    asm("mov.b64 %0, {%1, %2};" : "=l"(r) : "f"(lo), "f"(hi));
    return r;
}
__device__ __forceinline__ void upk2(unsigned long long v, float& lo, float& hi) {
    asm("mov.b64 {%0, %1}, %2;" : "=f"(lo), "=f"(hi) : "l"(v));
}
__device__ __forceinline__ unsigned long long fma2(unsigned long long a,
                                                   unsigned long long b,
                                                   unsigned long long c) {
    unsigned long long d;
    asm("fma.rn.f32x2 %0, %1, %2, %3;" : "=l"(d) : "l"(a), "l"(b), "l"(c));
    return d;
}
__device__ __forceinline__ unsigned long long mul2(unsigned long long a,
                                                   unsigned long long b) {
    unsigned long long d;
    asm("mul.rn.f32x2 %0, %1, %2;" : "=l"(d) : "l"(a), "l"(b));
    return d;
}

// ---------------- P0: symmetrize U3 over permutations -> g_P[t][k] ----------------
#define U3AT(a, b, d) U3[((((a) * II + (b)) * II + (d)) * NK3) + k]

__global__ void p0_kernel(const float* __restrict__ U3) {
    int idx = blockIdx.x * blockDim.x + threadIdx.x;
    if (idx >= NT3 * NK3) return;
    int t = idx / NK3, k = idx - t * NK3;
    // unrank t -> (p<=q<=j), enumeration order: p outer asc, then q, then j
    int p = 0, rem = t;
    while (rem >= (II - p) * (II - p + 1) / 2) { rem -= (II - p) * (II - p + 1) / 2; p++; }
    int q = p;
    while (rem >= II - q) { rem -= II - q; q++; }
    int j = q + rem;

    float s;
    if (p == q && q == j) {
        s = U3AT(p, p, p);
    } else if (p == q) {
        s = U3AT(p, p, j) + U3AT(p, j, p) + U3AT(j, p, p);
    } else if (q == j) {
        s = U3AT(p, q, q) + U3AT(q, p, q) + U3AT(q, q, p);
    } else {
        s = U3AT(p, q, j) + U3AT(p, j, q) + U3AT(q, p, j) +
            U3AT(q, j, p) + U3AT(j, p, q) + U3AT(j, q, p);
    }
    g_P[t * NK3 + k] = s;
}

// ---------------- P1: per-channel coefficient build ----------------
__global__ void p1_kernel(const float* __restrict__ U2, const float* __restrict__ U1,
                          const float* __restrict__ w3, const float* __restrict__ w2,
                          const float* __restrict__ w1) {
    int c = blockIdx.x;
    int tid = threadIdx.x;
    __shared__ float w3s[NK3];
    __shared__ float w2s[NK2];
    __shared__ float w1s;
    if (tid < NK3) w3s[tid] = w3[c * NK3 + tid];
    if (tid < NK2) w2s[tid] = w2[c * NK2 + tid];
    if (tid == 0)  w1s = w1[c];
    __syncthreads();

    unsigned long long* cc = g_coeff + (size_t)c * 1024;

    for (int t = tid; t < NT3; t += blockDim.x) {
        float s = 0.f;
#pragma unroll
        for (int k = 0; k < NK3; k++) s += g_P[t * NK3 + k] * w3s[k];
        cc[t] = pk2(s, s);
    }
    for (int u = tid; u < NT2; u += blockDim.x) {
        int p = 0, rem = u;
        while (rem >= II - p) { rem -= II - p; p++; }
        int q = p + rem;
        float s = 0.f;
#pragma unroll
        for (int k = 0; k < NK2; k++) {
            float v = (p == q) ? U2[(p * II + p) * NK2 + k]
                               : (U2[(p * II + q) * NK2 + k] + U2[(q * II + p) * NK2 + k]);
            s += w2s[k] * v;
        }
        cc[NT3 + u] = pk2(s, s);
    }
    for (int p = tid; p < II; p += blockDim.x) {
        float s = U1[p] * w1s;  // K1 == 1
        cc[NT3 + NT2 + p] = pk2(s, s);
    }
}

// ---------------- Main: symmetric contraction, 4 b's per thread, f32x2 math ----------------
__global__ __launch_bounds__(128) void main_kernel(const float* __restrict__ nf, int B) {
    __shared__ unsigned long long sco[NCOEFF];
    int c = blockIdx.y;
    const unsigned long long* cc = g_coeff + (size_t)c * 1024;
    for (int i = threadIdx.x; i < NCOEFF; i += blockDim.x) sco[i] = cc[i];
    __syncthreads();

    int b0 = (blockIdx.x * blockDim.x + threadIdx.x) * 4;
    if (b0 >= B) return;

    const float* x0 = nf + ((size_t)b0 * CI + c) * II;
    const size_t str = (size_t)CI * II;

    unsigned long long xA[II], xB[II];
#pragma unroll
    for (int i = 0; i < II; i += 4) {
        float4 a0 = *reinterpret_cast<const float4*>(x0 + i);
        float4 a1 = *reinterpret_cast<const float4*>(x0 + str + i);
        float4 a2 = *reinterpret_cast<const float4*>(x0 + 2 * str + i);
        float4 a3 = *reinterpret_cast<const float4*>(x0 + 3 * str + i);
        xA[i + 0] = pk2(a0.x, a1.x); xA[i + 1] = pk2(a0.y, a1.y);
        xA[i + 2] = pk2(a0.z, a1.z); xA[i + 3] = pk2(a0.w, a1.w);
        xB[i + 0] = pk2(a2.x, a3.x); xB[i + 1] = pk2(a2.y, a3.y);
        xB[i + 2] = pk2(a2.z, a3.z); xB[i + 3] = pk2(a2.w, a3.w);
    }

    unsigned long long accA = 0ull, accB = 0ull;   // packed (0.f, 0.f)
    int t = 0, u = 0;
#pragma unroll
    for (int p = 0; p < II; p++) {
#pragma unroll
        for (int q = p; q < II; q++) {
            unsigned long long c2v = sco[NT3 + u]; u++;
            unsigned long long pA = c2v, pB = c2v;
#pragma unroll
            for (int j = q; j < II; j++) {
                unsigned long long sv = sco[t]; t++;
                pA = fma2(xA[j], sv, pA);
                pB = fma2(xB[j], sv, pB);
            }
            unsigned long long xpqA = mul2(xA[p], xA[q]);
            unsigned long long xpqB = mul2(xB[p], xB[q]);
            accA = fma2(xpqA, pA, accA);
            accB = fma2(xpqB, pB, accB);
        }
    }
#pragma unroll
    for (int p = 0; p < II; p++) {
        unsigned long long c1v = sco[NT3 + NT2 + p];
        accA = fma2(xA[p], c1v, accA);
        accB = fma2(xB[p], c1v, accB);
    }

    float r0, r1, r2, r3;
    upk2(accA, r0, r1);
    upk2(accB, r2, r3);
    g_out1[(size_t)(b0 + 0) * CI + c] = r0;
    g_out1[(size_t)(b0 + 1) * CI + c] = r1;
    g_out1[(size_t)(b0 + 2) * CI + c] = r2;
    g_out1[(size_t)(b0 + 3) * CI + c] = r3;
}

// ---------------- o3.Linear: (B,C) @ (C,C) * 1/sqrt(C) ----------------
__global__ __launch_bounds__(256) void lin_kernel(const float* __restrict__ W,
                                                  float* __restrict__ O, int M) {
    __shared__ float As[16][64];
    __shared__ float Bs[16][64];
    int mb = blockIdx.x * 64, nb = blockIdx.y * 64;
    int tid = threadIdx.x;
    int tx = tid & 15, ty = tid >> 4;

    float acc[4][4] = {};
    for (int k0 = 0; k0 < CI; k0 += 16) {
#pragma unroll
        for (int l = tid; l < 1024; l += 256) {
            int m = l >> 4, k = l & 15;
            As[k][m] = g_out1[(size_t)(mb + m) * CI + k0 + k];
        }
#pragma unroll
        for (int l = tid; l < 1024; l += 256) {
            int k = l >> 6, n = l & 63;
            Bs[k][n] = W[(size_t)(k0 + k) * CI + nb + n];
        }
        __syncthreads();
#pragma unroll
        for (int kk = 0; kk < 16; kk++) {
            float a[4], b[4];
#pragma unroll
            for (int i = 0; i < 4; i++) a[i] = As[kk][ty * 4 + i];
#pragma unroll
            for (int j = 0; j < 4; j++) b[j] = Bs[kk][tx * 4 + j];
#pragma unroll
            for (int i = 0; i < 4; i++)
#pragma unroll
                for (int j = 0; j < 4; j++) acc[i][j] += a[i] * b[j];
        }
        __syncthreads();
    }
    const float inv = 0.0625f;   // 1/sqrt(256)
#pragma unroll
    for (int i = 0; i < 4; i++)
#pragma unroll
        for (int j = 0; j < 4; j++)
            O[(size_t)(mb + ty * 4 + i) * CI + nb + tx * 4 + j] = acc[i][j] * inv;
}

// ---------------- launch ----------------
extern "C" void kernel_launch(void* const* d_in, const int* in_sizes, int n_in,
                              void* d_out, int out_size) {
    const float* nf = (const float*)d_in[0];
    const float* U3 = (const float*)d_in[1];
    const float* U2 = (const float*)d_in[2];
    const float* U1 = (const float*)d_in[3];
    const float* w3 = (const float*)d_in[4];
    const float* w2 = (const float*)d_in[5];
    const float* w1 = (const float*)d_in[6];
    const float* WL = (const float*)d_in[7];
    float* out = (float*)d_out;

    int B = in_sizes[0] / (CI * II);   // 4096

    p0_kernel<<<(NT3 * NK3 + 255) / 256, 256>>>(U3);
    p1_kernel<<<CI, 128>>>(U2, U1, w3, w2, w1);
    main_kernel<<<dim3((B + 511) / 512, CI), 128>>>(nf, B);
    lin_kernel<<<dim3(B / 64, CI / 64), 256>>>(WL, out, B);
}